// round 17
// baseline (speedup 1.0000x reference)
#include <cuda_runtime.h>

#define BS     4096
#define SEGLEN 8192
#define LAM1   8e-05f
#define LAM2   8e-05f
#define TPB    256
#define NWARP  (TPB / 32)
#define BSCALE 16777216.0f   // 2^24 fixed-point scale for base accumulation

// Scratch (allocation-free rule: __device__ globals).
// All zero at load; finalize re-zeros them after use (graph-replay-safe).
__device__ int                g_nhist[SEGLEN];  // argmax hist over negative rows
__device__ int                g_phist[SEGLEN];  // argmax hist over positive rows
__device__ unsigned long long g_bsum;           // sum_pos base_i * 2^24

// ---------------------------------------------------------------------------
// Kernel 1: per-row stats (R16 structure — fastest measured). Publishes ONLY
// two histogram atomics + one int64 base-sum atomic; no per-row arrays.
// ---------------------------------------------------------------------------
__global__ __launch_bounds__(TPB) void row_stats(const float* __restrict__ scores,
                                                 const int*   __restrict__ labels) {
    const int row = blockIdx.x;
    const float*  rf = scores + (size_t)row * SEGLEN;
    const float4* rp = (const float4*)rf;
    const int t = threadIdx.x, lane = t & 31, w = t >> 5;

    // prefetch label early; consumed only in thread 0's tail
    int lb = 0;
    if (t == 0) lb = labels[row];

    float sum = 0.f, sq = 0.f, maxv = -1.f;
    int maxi = 0;

#pragma unroll
    for (int g = 0; g < 8; g++) {
        const int v4 = g * TPB + t;     // coalesced across lanes
        const int e  = v4 * 4;
        float4 x = rp[v4];
        float nxt = (e + 4 < SEGLEN) ? __ldg(rf + e + 4) : x.w;  // last: diff 0

        sum += (x.x + x.y) + (x.z + x.w);
        float d0 = x.y - x.x, d1 = x.z - x.y, d2 = x.w - x.z, d3 = nxt - x.w;
        sq += d0 * d0 + d1 * d1 + d2 * d2 + d3 * d3;

        // strict > preserves first occurrence (indices ascend within thread)
        if (x.x > maxv) { maxv = x.x; maxi = e;     }
        if (x.y > maxv) { maxv = x.y; maxi = e + 1; }
        if (x.z > maxv) { maxv = x.z; maxi = e + 2; }
        if (x.w > maxv) { maxv = x.w; maxi = e + 3; }
    }

    // warp reduce (fixed order -> deterministic); tie -> min element index
#pragma unroll
    for (int off = 16; off > 0; off >>= 1) {
        sum += __shfl_down_sync(0xFFFFFFFFu, sum, off);
        sq  += __shfl_down_sync(0xFFFFFFFFu, sq,  off);
        float ov = __shfl_down_sync(0xFFFFFFFFu, maxv, off);
        int   oi = __shfl_down_sync(0xFFFFFFFFu, maxi, off);
        if (ov > maxv || (ov == maxv && oi < maxi)) { maxv = ov; maxi = oi; }
    }

    __shared__ float ssum[NWARP], ssq[NWARP], smax[NWARP];
    __shared__ int   sidx[NWARP];
    if (lane == 0) { ssum[w] = sum; ssq[w] = sq; smax[w] = maxv; sidx[w] = maxi; }
    __syncthreads();

    if (t == 0) {
        float S = 0.f, Q = 0.f, M = -1.f;
        int I = 0;
#pragma unroll
        for (int i = 0; i < NWARP; i++) {
            S += ssum[i];
            Q += ssq[i];
            if (smax[i] > M || (smax[i] == M && sidx[i] < I)) { M = smax[i]; I = sidx[i]; }
        }
        if (lb == 0) {
            atomicAdd(&g_nhist[I], 1);
        } else {
            atomicAdd(&g_phist[I], 1);
            float base = LAM1 * Q + LAM2 * S;   // > 0 always
            unsigned long long fx = (unsigned long long)llrintf(base * BSCALE);
            atomicAdd(&g_bsum, fx);             // int atomics -> deterministic
        }
    }
    __syncthreads();
    cudaTriggerProgrammaticLaunchCompletion();
}

// ---------------------------------------------------------------------------
// Kernel 2 (single block, 1024 threads, PDL):
//   L*BS = bsum/2^24 + sum_m P[m]*T[m], T[m] = S1[m] - m*S0[m] over N-hist.
//   One fused suffix scan of (S0,S1); P*T accumulated in registers during the
//   descending pass (no Tm array, no gather). Self-cleans all scratch.
// ---------------------------------------------------------------------------
__global__ __launch_bounds__(1024) void finalize(float* __restrict__ out) {
    __shared__ int       wt0[32], wt1[32], wo0[32], wo1[32];
    __shared__ long long red[32];

    const int t = threadIdx.x;
    const int lane = t & 31, w = t >> 5;
    const int base = t * 8;          // this thread owns bins [8t, 8t+8)

    // wait for row_stats results
    cudaGridDependencySynchronize();

    // coalesced int4 loads of this thread's 8 neg-hist + 8 pos-hist bins (L2-hot)
    int4 n0 = ((const int4*)g_nhist)[2 * t];
    int4 n1 = ((const int4*)g_nhist)[2 * t + 1];
    int4 p0 = ((const int4*)g_phist)[2 * t];
    int4 p1 = ((const int4*)g_phist)[2 * t + 1];

    int nh[8] = {n0.x, n0.y, n0.z, n0.w, n1.x, n1.y, n1.z, n1.w};
    int ph[8] = {p0.x, p0.y, p0.z, p0.w, p1.x, p1.y, p1.z, p1.w};

    // chunk totals: c0 = sum n, c1 = sum n*(bin+1)
    int c0 = 0, c1 = 0;
#pragma unroll
    for (int k = 0; k < 8; k++) { c0 += nh[k]; c1 += nh[k] * (base + k + 1); }

    // warp inclusive suffix scan of (c0, c1)
    int i0 = c0, i1 = c1;
#pragma unroll
    for (int off = 1; off < 32; off <<= 1) {
        int v0 = __shfl_down_sync(0xFFFFFFFFu, i0, off);
        int v1 = __shfl_down_sync(0xFFFFFFFFu, i1, off);
        if (lane + off < 32) { i0 += v0; i1 += v1; }
    }
    if (lane == 0) { wt0[w] = i0; wt1[w] = i1; }
    __syncthreads();

    // warp 0: exclusive suffix over 32 warp totals (both components)
    if (w == 0) {
        int v0 = wt0[lane], v1 = wt1[lane];
        int s0 = v0, s1 = v1;
#pragma unroll
        for (int off = 1; off < 32; off <<= 1) {
            int u0 = __shfl_down_sync(0xFFFFFFFFu, s0, off);
            int u1 = __shfl_down_sync(0xFFFFFFFFu, s1, off);
            if (lane + off < 32) { s0 += u0; s1 += u1; }
        }
        wo0[lane] = s0 - v0;  // sum of warps strictly after lane
        wo1[lane] = s1 - v1;
    }
    __syncthreads();

    // descending within chunk: T[bin] = r1 - bin*r0; accumulate P[bin]*T[bin]
    int r0 = (i0 - c0) + wo0[w];
    int r1 = (i1 - c1) + wo1[w];
    long long acc = 0;
#pragma unroll
    for (int k = 7; k >= 0; k--) {
        const int bin = base + k;
        r0 += nh[k];
        r1 += nh[k] * (bin + 1);
        acc += (long long)ph[k] * (long long)(r1 - bin * r0);
    }

    // self-clean hists for next graph replay
    ((int4*)g_nhist)[2 * t]     = make_int4(0, 0, 0, 0);
    ((int4*)g_nhist)[2 * t + 1] = make_int4(0, 0, 0, 0);
    ((int4*)g_phist)[2 * t]     = make_int4(0, 0, 0, 0);
    ((int4*)g_phist)[2 * t + 1] = make_int4(0, 0, 0, 0);

    // deterministic int64 tree reduction
#pragma unroll
    for (int off = 16; off > 0; off >>= 1)
        acc += __shfl_down_sync(0xFFFFFFFFu, acc, off);
    if (lane == 0) red[w] = acc;
    __syncthreads();
    if (w == 0) {
        long long v = red[lane];
#pragma unroll
        for (int off = 16; off > 0; off >>= 1)
            v += __shfl_down_sync(0xFFFFFFFFu, v, off);
        if (lane == 0) {
            double total = (double)v + (double)g_bsum / (double)BSCALE;
            out[0] = (float)(total / (double)BS);
            g_bsum = 0ull;  // reset for next replay
        }
    }
}

extern "C" void kernel_launch(void* const* d_in, const int* in_sizes, int n_in,
                              void* d_out, int out_size) {
    const float* scores = (const float*)d_in[0];
    const int*   labels = (const int*)d_in[1];
    float*       out    = (float*)d_out;

    row_stats<<<BS, TPB>>>(scores, labels);

    // finalize with Programmatic Dependent Launch
    cudaLaunchConfig_t cfg = {};
    cfg.gridDim  = dim3(1, 1, 1);
    cfg.blockDim = dim3(1024, 1, 1);
    cfg.dynamicSmemBytes = 0;
    cudaLaunchAttribute attrs[1];
    attrs[0].id = cudaLaunchAttributeProgrammaticStreamSerialization;
    attrs[0].val.programmaticStreamSerializationAllowed = 1;
    cfg.attrs = attrs;
    cfg.numAttrs = 1;
    cudaLaunchKernelEx(&cfg, finalize, out);
}